// round 10
// baseline (speedup 1.0000x reference)
#include <cuda_runtime.h>
#include <cstdint>

// ---------------- problem constants ----------------
#define FH_   100
#define FW_   160
#define NPOS  16000          // FH*FW
#define CIN   512
#define KTOT  4608           // 9*512
#define NANCH 144000         // NPOS*9
#define PRE_NMS_  6000
#define POST_NMS_ 300
#define IMG_H 1600.0f
#define IMG_W 2560.0f

#define OFF_SCORES 0
#define OFF_REG    144000
#define OFF_PROPS  720000

#define NBLK 148             // persistent-select grid (1 CTA/SM, residency guaranteed)

// ---------------- scratch (device globals; no allocation allowed) ----------------
__device__ float              g_AT[(size_t)KTOT * NPOS];  // 295MB zero-padded im2col^T
__device__ float              g_y[NPOS * 512];            // conv1 output
__device__ float              g_wT[45 * 512];             // head weights transposed [o][k]
__device__ float4             g_props[NANCH];
__device__ unsigned long long g_keys[NANCH];
__device__ unsigned long long g_cand_keys[PRE_NMS_];
__device__ float4             g_cand_boxes[PRE_NMS_];
__device__ unsigned int       g_hist[256];
__device__ unsigned long long g_prefix;
__device__ unsigned int       g_done;
__device__ unsigned int       g_bar;
__device__ unsigned int       g_count;

// ---------------- helpers ----------------
__device__ __forceinline__ uint32_t s2u(const void* p) {
    uint32_t a;
    asm("{ .reg .u64 t; cvta.to.shared.u64 t, %1; cvt.u32.u64 %0, t; }" : "=r"(a) : "l"(p));
    return a;
}
__device__ __forceinline__ void cp16(uint32_t dst, const void* src) {
    asm volatile("cp.async.cg.shared.global [%0], [%1], 16;" :: "r"(dst), "l"(src));
}
// software grid barrier: atomic arrive, volatile poll (cooperative-groups pattern)
__device__ __forceinline__ void gbar(int ph) {
    __syncthreads();
    if (threadIdx.x == 0) {
        __threadfence();
        atomicAdd(&g_bar, 1u);
        volatile unsigned int* vb = &g_bar;
        while (*vb < (unsigned)(ph * NBLK)) { }
    }
    __syncthreads();
}

// ---------------- reset ----------------
__global__ void k_reset() {
    int t = threadIdx.x;
    if (t < 256) g_hist[t] = 0u;
    if (t == 0) { g_prefix = 0ull; g_done = 0u; g_bar = 0u; g_count = 0u; }
}

// ---------------- prep: transpose head weights into wT[45][512] ----------------
__global__ void k_prep_w(const float* __restrict__ Wc, const float* __restrict__ Wr) {
    for (int i = blockIdx.x * 256 + threadIdx.x; i < 45 * 512; i += gridDim.x * 256) {
        int o = i >> 9, k = i & 511;
        g_wT[o * 512 + k] = (o < 9) ? Wc[k * 9 + o] : Wr[k * 36 + (o - 9)];
    }
}

// ---------------- prep: build zero-padded im2col transpose AT[k][m] ----------------
__global__ __launch_bounds__(256)
void k_prep(const float* __restrict__ fm) {
    __shared__ float ts[32][33];
    const int tx = threadIdx.x;      // 0..31
    const int ty = threadIdx.y;      // 0..7
    const int m0  = blockIdx.x * 32;
    const int ci0 = blockIdx.y * 32;
    const int tap = blockIdx.z;
    const int dh = tap / 3 - 1, dw = tap % 3 - 1;
    const int delta = dh * FW_ + dw;

    for (int r = ty; r < 32; r += 8) {
        int m = m0 + r;
        int h = m / FW_, w = m % FW_;
        bool ok = ((unsigned)(h + dh) < FH_) && ((unsigned)(w + dw) < FW_);
        ts[r][tx] = ok ? fm[(size_t)(m + delta) * 512 + ci0 + tx] : 0.f;
    }
    __syncthreads();
    for (int r = ty; r < 32; r += 8) {
        g_AT[(size_t)(tap * 512 + ci0 + r) * NPOS + m0 + tx] = ts[tx][r];
    }
}

// ---------------- 3x3 conv as GEMM: C[16000,512] = AT^T * W1 (UNCHANGED, bit-exact) ----
#define BK   16
#define NKT  (KTOT / BK)     // 288

__global__ __launch_bounds__(256, 2)
void k_conv3(const float* __restrict__ W1, const float* __restrict__ b1) {
    __shared__ float As[3][BK][128];
    __shared__ float Bs[3][BK][128];

    const int t  = threadIdx.x;
    const int m0 = blockIdx.x * 128;
    const int n0 = blockIdx.y * 128;
    const int tx = t & 15, ty = t >> 4;

    float acc[8][8];
#pragma unroll
    for (int i = 0; i < 8; ++i)
#pragma unroll
        for (int j = 0; j < 8; ++j) acc[i][j] = 0.f;

    auto loads = [&](int kt, int stg) {
        int K0 = kt * BK;
#pragma unroll
        for (int s = 0; s < 2; ++s) {
            int c  = t + s * 256;
            int k  = c >> 5;
            int mc = (c & 31) * 4;
            cp16(s2u(&As[stg][k][mc]), g_AT + (size_t)(K0 + k) * NPOS + m0 + mc);
            cp16(s2u(&Bs[stg][k][mc]), W1 + (size_t)(K0 + k) * 512 + n0 + mc);
        }
        asm volatile("cp.async.commit_group;" ::: "memory");
    };

    loads(0, 0);
    loads(1, 1);

    for (int kt = 0; kt < NKT; ++kt) {
        if (kt == NKT - 1) asm volatile("cp.async.wait_group 0;" ::: "memory");
        else               asm volatile("cp.async.wait_group 1;" ::: "memory");
        __syncthreads();
        if (kt + 2 < NKT) loads(kt + 2, (kt + 2) % 3);

        const int stg = kt % 3;
#pragma unroll
        for (int k = 0; k < BK; ++k) {
            float4 a0  = *(float4*)&As[stg][k][ty * 8];
            float4 a1  = *(float4*)&As[stg][k][ty * 8 + 4];
            float4 b0  = *(float4*)&Bs[stg][k][tx * 8];
            float4 b1v = *(float4*)&Bs[stg][k][tx * 8 + 4];
            float av[8] = {a0.x, a0.y, a0.z, a0.w, a1.x, a1.y, a1.z, a1.w};
            float bv[8] = {b0.x, b0.y, b0.z, b0.w, b1v.x, b1v.y, b1v.z, b1v.w};
#pragma unroll
            for (int i = 0; i < 8; ++i)
#pragma unroll
                for (int j = 0; j < 8; ++j) acc[i][j] += av[i] * bv[j];
        }
        __syncthreads();
    }

    float bs[8];
#pragma unroll
    for (int j = 0; j < 8; ++j) bs[j] = b1[n0 + tx * 8 + j];

#pragma unroll
    for (int i = 0; i < 8; ++i) {
        int pos = m0 + ty * 8 + i;
        float o[8];
#pragma unroll
        for (int j = 0; j < 8; ++j) o[j] = fmaxf(acc[i][j] + bs[j], 0.f);
        float* dst = g_y + (size_t)pos * 512 + n0 + tx * 8;
        *(float4*)(dst)     = make_float4(o[0], o[1], o[2], o[3]);
        *(float4*)(dst + 4) = make_float4(o[4], o[5], o[6], o[7]);
    }
}

// ---------------- 1x1 head convs + sigmoid (broadcast mapping, UNCHANGED) -----------
#define SYROW 516
__global__ __launch_bounds__(256)
void k_head(const float* __restrict__ bc, const float* __restrict__ br,
            float* __restrict__ out) {
    __shared__ float sy[16 * SYROW];
    const int t  = threadIdx.x;
    const int p0 = blockIdx.x * 16;

    {
        const float4* src = (const float4*)(g_y + (size_t)p0 * 512);
        for (int i = t; i < 16 * 128; i += 256) {
            int pos = i >> 7, c = i & 127;
            ((float4*)(sy + pos * SYROW))[c] = src[i];
        }
    }
    __syncthreads();

    const int oBase = t >> 4;
    const int pos   = t & 15;
#pragma unroll
    for (int r = 0; r < 3; ++r) {
        int o = r * 16 + oBase;
        if (o < 45) {
            const float4* y4 = (const float4*)(sy + pos * SYROW);
            const float4* w4 = (const float4*)(g_wT + o * 512);
            float acc = 0.f;
#pragma unroll 4
            for (int k4 = 0; k4 < 128; ++k4) {
                float4 yv = y4[k4];
                float4 wv = w4[k4];
                acc += yv.x * wv.x;
                acc += yv.y * wv.y;
                acc += yv.z * wv.z;
                acc += yv.w * wv.w;
            }
            int gp = p0 + pos;
            if (o < 9) {
                acc += bc[o];
                out[OFF_SCORES + gp * 9 + o] = 1.f / (1.f + expf(-acc));
            } else {
                acc += br[o - 9];
                out[OFF_REG + gp * 36 + (o - 9)] = acc;
            }
        }
    }
}

// ---------------- fused select: decode + 8x(hist/scan) + compact, one launch --------
__global__ __launch_bounds__(256)
void k_select(const float* __restrict__ am, const float* __restrict__ out) {
    __shared__ unsigned int sh[256];
    __shared__ unsigned long long s_pref;
    __shared__ unsigned int s_done;

    const int t = threadIdx.x;
    const int gid = blockIdx.x * 256 + t;
    const int stride = NBLK * 256;

    // ---- phase A: decode anchors + build sort keys (own slice) ----
    for (int i = gid; i < NANCH; i += stride) {
        float  s = out[OFF_SCORES + i];
        float4 d = *(const float4*)(out + OFF_REG + (size_t)i * 4);
        float4 A = *(const float4*)(am + (size_t)i * 4);
        float ah = A.z - A.x, aw = A.w - A.y;
        float acy = A.x + 0.5f * ah, acx = A.y + 0.5f * aw;
        float cy = acy + d.x * ah, cx = acx + d.y * aw;
        float hh = ah * expf(d.z), ww = aw * expf(d.w);
        g_props[i] = make_float4(cy - 0.5f * hh, cx - 0.5f * ww, cy + 0.5f * hh, cx + 0.5f * ww);
        unsigned int ob = __float_as_uint(s) | 0x80000000u;
        g_keys[i] = ((unsigned long long)ob << 32) |
                    (unsigned long long)(0xFFFFFFFFu - (unsigned)i);
    }
    int ph = 1;
    gbar(ph);

    // block0's scan state lives in registers
    unsigned long long prefix = 0ull;
    unsigned int rank = PRE_NMS_;

    // ---- phases B: 8 radix passes (early-exit when boundary bucket == need) ----
    for (int b = 7; b >= 0; --b) {
        if (t == 0) {
            s_done = atomicAdd(&g_done, 0u);
            s_pref = atomicAdd(&g_prefix, 0ull);
        }
        __syncthreads();
        if (!s_done) {
            sh[t] = 0u;
            __syncthreads();
            unsigned long long pref = s_pref;
            int shift = (b + 1) * 8;
            for (int i = gid; i < NANCH; i += stride) {
                unsigned long long k = g_keys[i];
                if (b == 7 || (k >> shift) == (pref >> shift))
                    atomicAdd(&sh[(unsigned int)(k >> (b * 8)) & 255u], 1u);
            }
            __syncthreads();
            if (sh[t]) atomicAdd(&g_hist[t], sh[t]);
        }
        gbar(++ph);
        if (blockIdx.x == 0 && t == 0 && !s_done) {
            unsigned int cum = 0, c = 0;
            int d = 255;
            for (; d >= 0; --d) {
                c = atomicAdd(&g_hist[d], 0u);
                if (cum + c >= rank) break;
                cum += c;
            }
            if (d < 0) { d = 0; c = 0; }
            prefix |= ((unsigned long long)(unsigned int)d) << (b * 8);
            unsigned int need = rank - cum;
            rank = need;
            atomicExch(&g_prefix, prefix);
            if (c == need) atomicExch(&g_done, 1u);   // threshold exact with low bits 0
            for (int j = 0; j < 256; ++j) atomicExch(&g_hist[j], 0u);
        }
        gbar(++ph);
    }

    // ---- phase C: compact top-6000, clip + min-size filter (own slice) ----
    unsigned long long thr;
    if (t == 0) s_pref = atomicAdd(&g_prefix, 0ull);
    __syncthreads();
    thr = s_pref;
    for (int i = gid; i < NANCH; i += stride) {
        unsigned long long k = g_keys[i];
        if (k >= thr) {
            unsigned int slot = atomicAdd(&g_count, 1u);
            float4 pr = g_props[i];
            float y1 = fmaxf(pr.x, 0.f), x1 = fmaxf(pr.y, 0.f);
            float y2 = fminf(pr.z, IMG_H), x2 = fminf(pr.w, IMG_W);
            float hh = y2 - y1, ww = x2 - x1;
            if (!(hh >= 16.f && ww >= 16.f)) k = 0ull;
            g_cand_keys[slot]  = k;
            g_cand_boxes[slot] = make_float4(y1, x1, y2, x2);
        }
    }
}

// ---------------- greedy NMS: single block, register-resident (UNCHANGED) -----------
__global__ __launch_bounds__(1024)
void k_nms(float* __restrict__ out) {
    __shared__ unsigned long long wmax[32];
    __shared__ unsigned long long smax;
    __shared__ float4 ssel;

    const int t = threadIdx.x, lane = t & 31, warp = t >> 5;
    unsigned long long lk[6];
    float4 lb[6];
#pragma unroll
    for (int e = 0; e < 6; ++e) {
        int idx = e * 1024 + t;
        if (idx < PRE_NMS_) { lk[e] = g_cand_keys[idx]; lb[e] = g_cand_boxes[idx]; }
        else                { lk[e] = 0ull; lb[e] = make_float4(0.f, 0.f, 0.f, 0.f); }
    }
    float* outp = out + OFF_PROPS;

    for (int it = 0; it < POST_NMS_; ++it) {
        unsigned long long m = lk[0];
#pragma unroll
        for (int e = 1; e < 6; ++e) m = (lk[e] > m) ? lk[e] : m;
#pragma unroll
        for (int o = 16; o > 0; o >>= 1) {
            unsigned long long v = __shfl_down_sync(0xffffffffu, m, o);
            if (v > m) m = v;
        }
        if (lane == 0) wmax[warp] = m;
        __syncthreads();
        if (warp == 0) {
            unsigned long long v = wmax[lane];
#pragma unroll
            for (int o = 16; o > 0; o >>= 1) {
                unsigned long long v2 = __shfl_down_sync(0xffffffffu, v, o);
                if (v2 > v) v = v2;
            }
            if (lane == 0) smax = v;
        }
        __syncthreads();
        unsigned long long gm = smax;

        if (gm == 0ull) {
            if (t == 0) *(float4*)(outp + it * 4) = make_float4(0.f, 0.f, 0.f, 0.f);
            __syncthreads();
            continue;
        }
#pragma unroll
        for (int e = 0; e < 6; ++e) {
            if (lk[e] == gm) {
                ssel = lb[e];
                *(float4*)(outp + it * 4) = lb[e];
                lk[e] = 0ull;
            }
        }
        __syncthreads();
        float4 s = ssel;
        float sa = fmaxf(s.z - s.x, 0.f) * fmaxf(s.w - s.y, 0.f);
#pragma unroll
        for (int e = 0; e < 6; ++e) {
            if (lk[e] != 0ull) {
                float yy1 = fmaxf(s.x, lb[e].x);
                float xx1 = fmaxf(s.y, lb[e].y);
                float yy2 = fminf(s.z, lb[e].z);
                float xx2 = fminf(s.w, lb[e].w);
                float inter = fmaxf(yy2 - yy1, 0.f) * fmaxf(xx2 - xx1, 0.f);
                float a2 = fmaxf(lb[e].z - lb[e].x, 0.f) * fmaxf(lb[e].w - lb[e].y, 0.f);
                float iou = inter / (sa + a2 - inter + 1e-8f);
                if (iou > 0.7f) lk[e] = 0ull;
            }
        }
        __syncthreads();
    }
}

// ---------------- launch ----------------
extern "C" void kernel_launch(void* const* d_in, const int* in_sizes, int n_in,
                              void* d_out, int out_size) {
    const float* fm = (const float*)d_in[1];
    const float* am = (const float*)d_in[2];
    const float* W1 = (const float*)d_in[4];
    const float* b1 = (const float*)d_in[5];
    const float* Wc = (const float*)d_in[6];
    const float* bc = (const float*)d_in[7];
    const float* Wr = (const float*)d_in[8];
    const float* br = (const float*)d_in[9];
    float* out = (float*)d_out;

    k_reset<<<1, 256>>>();
    k_prep_w<<<12, 256>>>(Wc, Wr);
    k_prep<<<dim3(500, 16, 9), dim3(32, 8)>>>(fm);
    k_conv3<<<dim3(125, 4), 256>>>(W1, b1);
    k_head<<<1000, 256>>>(bc, br, out);
    k_select<<<NBLK, 256>>>(am, out);
    k_nms<<<1, 1024>>>(out);
}

// round 11
// speedup vs baseline: 1.0332x; 1.0332x over previous
#include <cuda_runtime.h>
#include <cstdint>

// ---------------- problem constants ----------------
#define FH_   100
#define FW_   160
#define NPOS  16000          // FH*FW
#define CIN   512
#define KTOT  4608           // 9*512
#define NANCH 144000         // NPOS*9
#define PRE_NMS_  6000
#define POST_NMS_ 300
#define IMG_H 1600.0f
#define IMG_W 2560.0f

#define OFF_SCORES 0
#define OFF_REG    144000
#define OFF_PROPS  720000

// ---------------- scratch (device globals; no allocation allowed) ----------------
__device__ float              g_AT[(size_t)KTOT * NPOS];  // 295MB zero-padded im2col^T
__device__ float              g_y[NPOS * 512];            // conv1 output
__device__ float              g_wT[45 * 512];             // head weights transposed [o][k]
__device__ float4             g_props[NANCH];
__device__ unsigned long long g_keys[NANCH];
__device__ unsigned long long g_cand_keys[PRE_NMS_];
__device__ float4             g_cand_boxes[PRE_NMS_];
__device__ unsigned int       g_hist[256];
__device__ unsigned long long g_prefix;
__device__ unsigned int       g_rank;
__device__ unsigned int       g_done;
__device__ unsigned int       g_count;

// ---------------- helpers ----------------
__device__ __forceinline__ uint32_t s2u(const void* p) {
    uint32_t a;
    asm("{ .reg .u64 t; cvta.to.shared.u64 t, %1; cvt.u32.u64 %0, t; }" : "=r"(a) : "l"(p));
    return a;
}
__device__ __forceinline__ void cp16(uint32_t dst, const void* src) {
    asm volatile("cp.async.cg.shared.global [%0], [%1], 16;" :: "r"(dst), "l"(src));
}

// ---------------- reset + head-weight transpose (merged) ----------------
__global__ void k_reset(const float* __restrict__ Wc, const float* __restrict__ Wr) {
    int t = blockIdx.x * 256 + threadIdx.x;
    if (t < 256) g_hist[t] = 0u;
    if (t == 0) { g_prefix = 0ull; g_rank = PRE_NMS_; g_done = 0u; g_count = 0u; }
    for (int i = t; i < 45 * 512; i += gridDim.x * 256) {
        int o = i >> 9, k = i & 511;
        g_wT[o * 512 + k] = (o < 9) ? Wc[k * 9 + o] : Wr[k * 36 + (o - 9)];
    }
}

// ---------------- prep: build zero-padded im2col transpose AT[k][m] ----------------
__global__ __launch_bounds__(256)
void k_prep(const float* __restrict__ fm) {
    __shared__ float ts[32][33];
    const int tx = threadIdx.x;      // 0..31
    const int ty = threadIdx.y;      // 0..7
    const int m0  = blockIdx.x * 32;
    const int ci0 = blockIdx.y * 32;
    const int tap = blockIdx.z;
    const int dh = tap / 3 - 1, dw = tap % 3 - 1;
    const int delta = dh * FW_ + dw;

    for (int r = ty; r < 32; r += 8) {
        int m = m0 + r;
        int h = m / FW_, w = m % FW_;
        bool ok = ((unsigned)(h + dh) < FH_) && ((unsigned)(w + dw) < FW_);
        ts[r][tx] = ok ? fm[(size_t)(m + delta) * 512 + ci0 + tx] : 0.f;
    }
    __syncthreads();
    for (int r = ty; r < 32; r += 8) {
        g_AT[(size_t)(tap * 512 + ci0 + r) * NPOS + m0 + tx] = ts[tx][r];
    }
}

// ---------------- 3x3 conv as GEMM: C[16000,512] = AT^T * W1 (UNCHANGED, bit-exact) ----
#define BK   16
#define NKT  (KTOT / BK)     // 288

__global__ __launch_bounds__(256, 2)
void k_conv3(const float* __restrict__ W1, const float* __restrict__ b1) {
    __shared__ float As[3][BK][128];
    __shared__ float Bs[3][BK][128];

    const int t  = threadIdx.x;
    const int m0 = blockIdx.x * 128;
    const int n0 = blockIdx.y * 128;
    const int tx = t & 15, ty = t >> 4;

    float acc[8][8];
#pragma unroll
    for (int i = 0; i < 8; ++i)
#pragma unroll
        for (int j = 0; j < 8; ++j) acc[i][j] = 0.f;

    auto loads = [&](int kt, int stg) {
        int K0 = kt * BK;
#pragma unroll
        for (int s = 0; s < 2; ++s) {
            int c  = t + s * 256;
            int k  = c >> 5;
            int mc = (c & 31) * 4;
            cp16(s2u(&As[stg][k][mc]), g_AT + (size_t)(K0 + k) * NPOS + m0 + mc);
            cp16(s2u(&Bs[stg][k][mc]), W1 + (size_t)(K0 + k) * 512 + n0 + mc);
        }
        asm volatile("cp.async.commit_group;" ::: "memory");
    };

    loads(0, 0);
    loads(1, 1);

    for (int kt = 0; kt < NKT; ++kt) {
        if (kt == NKT - 1) asm volatile("cp.async.wait_group 0;" ::: "memory");
        else               asm volatile("cp.async.wait_group 1;" ::: "memory");
        __syncthreads();
        if (kt + 2 < NKT) loads(kt + 2, (kt + 2) % 3);

        const int stg = kt % 3;
#pragma unroll
        for (int k = 0; k < BK; ++k) {
            float4 a0  = *(float4*)&As[stg][k][ty * 8];
            float4 a1  = *(float4*)&As[stg][k][ty * 8 + 4];
            float4 b0  = *(float4*)&Bs[stg][k][tx * 8];
            float4 b1v = *(float4*)&Bs[stg][k][tx * 8 + 4];
            float av[8] = {a0.x, a0.y, a0.z, a0.w, a1.x, a1.y, a1.z, a1.w};
            float bv[8] = {b0.x, b0.y, b0.z, b0.w, b1v.x, b1v.y, b1v.z, b1v.w};
#pragma unroll
            for (int i = 0; i < 8; ++i)
#pragma unroll
                for (int j = 0; j < 8; ++j) acc[i][j] += av[i] * bv[j];
        }
        __syncthreads();
    }

    float bs[8];
#pragma unroll
    for (int j = 0; j < 8; ++j) bs[j] = b1[n0 + tx * 8 + j];

#pragma unroll
    for (int i = 0; i < 8; ++i) {
        int pos = m0 + ty * 8 + i;
        float o[8];
#pragma unroll
        for (int j = 0; j < 8; ++j) o[j] = fmaxf(acc[i][j] + bs[j], 0.f);
        float* dst = g_y + (size_t)pos * 512 + n0 + tx * 8;
        *(float4*)(dst)     = make_float4(o[0], o[1], o[2], o[3]);
        *(float4*)(dst + 4) = make_float4(o[4], o[5], o[6], o[7]);
    }
}

// ---------------- 1x1 head convs + sigmoid (broadcast mapping, UNCHANGED) -----------
#define SYROW 516
__global__ __launch_bounds__(256)
void k_head(const float* __restrict__ bc, const float* __restrict__ br,
            float* __restrict__ out) {
    __shared__ float sy[16 * SYROW];
    const int t  = threadIdx.x;
    const int p0 = blockIdx.x * 16;

    {
        const float4* src = (const float4*)(g_y + (size_t)p0 * 512);
        for (int i = t; i < 16 * 128; i += 256) {
            int pos = i >> 7, c = i & 127;
            ((float4*)(sy + pos * SYROW))[c] = src[i];
        }
    }
    __syncthreads();

    const int oBase = t >> 4;
    const int pos   = t & 15;
#pragma unroll
    for (int r = 0; r < 3; ++r) {
        int o = r * 16 + oBase;
        if (o < 45) {
            const float4* y4 = (const float4*)(sy + pos * SYROW);
            const float4* w4 = (const float4*)(g_wT + o * 512);
            float acc = 0.f;
#pragma unroll 4
            for (int k4 = 0; k4 < 128; ++k4) {
                float4 yv = y4[k4];
                float4 wv = w4[k4];
                acc += yv.x * wv.x;
                acc += yv.y * wv.y;
                acc += yv.z * wv.z;
                acc += yv.w * wv.w;
            }
            int gp = p0 + pos;
            if (o < 9) {
                acc += bc[o];
                out[OFF_SCORES + gp * 9 + o] = 1.f / (1.f + expf(-acc));
            } else {
                acc += br[o - 9];
                out[OFF_REG + gp * 36 + (o - 9)] = acc;
            }
        }
    }
}

// ---------------- decode anchors + build sort keys ----------------
__global__ void k_decode(const float* __restrict__ am, const float* __restrict__ out) {
    int i = blockIdx.x * 256 + threadIdx.x;
    if (i >= NANCH) return;
    float  s = out[OFF_SCORES + i];
    float4 d = *(const float4*)(out + OFF_REG + (size_t)i * 4);
    float4 A = *(const float4*)(am + (size_t)i * 4);

    float ah = A.z - A.x, aw = A.w - A.y;
    float acy = A.x + 0.5f * ah, acx = A.y + 0.5f * aw;
    float cy = acy + d.x * ah, cx = acx + d.y * aw;
    float hh = ah * expf(d.z), ww = aw * expf(d.w);
    g_props[i] = make_float4(cy - 0.5f * hh, cx - 0.5f * ww, cy + 0.5f * hh, cx + 0.5f * ww);

    unsigned int ob = __float_as_uint(s) | 0x80000000u;
    g_keys[i] = ((unsigned long long)ob << 32) | (unsigned long long)(0xFFFFFFFFu - (unsigned)i);
}

// ---------------- exact top-6000: MSD radix select with early exit ----------------
__global__ void k_hist(int b) {
    __shared__ unsigned int sh[256];
    __shared__ unsigned int s_done;
    int t = threadIdx.x;
    if (t == 0) s_done = g_done;
    if (t < 256) sh[t] = 0u;
    __syncthreads();
    if (s_done) return;                       // threshold already exact
    unsigned long long pref = g_prefix;
    int shift = (b + 1) * 8;
    for (int i = blockIdx.x * blockDim.x + t; i < NANCH; i += gridDim.x * blockDim.x) {
        unsigned long long k = g_keys[i];
        if (b == 7 || (k >> shift) == (pref >> shift))
            atomicAdd(&sh[(unsigned int)(k >> (b * 8)) & 255u], 1u);
    }
    __syncthreads();
    if (t < 256 && sh[t]) atomicAdd(&g_hist[t], sh[t]);
}

__global__ void k_scan(int b) {
    if (threadIdx.x != 0) return;
    if (g_done) return;
    unsigned int r = g_rank, cum = 0, c = 0;
    int d = 255;
    for (; d >= 0; --d) {
        c = g_hist[d];
        if (cum + c >= r) break;
        cum += c;
    }
    if (d < 0) { d = 0; c = 0; }
    g_prefix |= ((unsigned long long)(unsigned int)d) << (b * 8);
    unsigned int need = r - cum;
    g_rank = need;
    // boundary bucket fully selected -> low-bytes-zero threshold is already exact
    if (c == need) g_done = 1u;
    for (int j = 0; j < 256; ++j) g_hist[j] = 0u;
}

// ---------------- compact top-6000, clip + min-size filter ----------------
__global__ void k_compact() {
    int i = blockIdx.x * 256 + threadIdx.x;
    if (i >= NANCH) return;
    unsigned long long k = g_keys[i];
    if (k >= g_prefix) {
        unsigned int slot = atomicAdd(&g_count, 1u);
        float4 pr = g_props[i];
        float y1 = fmaxf(pr.x, 0.f), x1 = fmaxf(pr.y, 0.f);
        float y2 = fminf(pr.z, IMG_H), x2 = fminf(pr.w, IMG_W);
        float hh = y2 - y1, ww = x2 - x1;
        if (!(hh >= 16.f && ww >= 16.f)) k = 0ull;
        g_cand_keys[slot]  = k;
        g_cand_boxes[slot] = make_float4(y1, x1, y2, x2);
    }
}

// ---------------- greedy NMS: single block, register-resident (UNCHANGED) -----------
__global__ __launch_bounds__(1024)
void k_nms(float* __restrict__ out) {
    __shared__ unsigned long long wmax[32];
    __shared__ unsigned long long smax;
    __shared__ float4 ssel;

    const int t = threadIdx.x, lane = t & 31, warp = t >> 5;
    unsigned long long lk[6];
    float4 lb[6];
#pragma unroll
    for (int e = 0; e < 6; ++e) {
        int idx = e * 1024 + t;
        if (idx < PRE_NMS_) { lk[e] = g_cand_keys[idx]; lb[e] = g_cand_boxes[idx]; }
        else                { lk[e] = 0ull; lb[e] = make_float4(0.f, 0.f, 0.f, 0.f); }
    }
    float* outp = out + OFF_PROPS;

    for (int it = 0; it < POST_NMS_; ++it) {
        unsigned long long m = lk[0];
#pragma unroll
        for (int e = 1; e < 6; ++e) m = (lk[e] > m) ? lk[e] : m;
#pragma unroll
        for (int o = 16; o > 0; o >>= 1) {
            unsigned long long v = __shfl_down_sync(0xffffffffu, m, o);
            if (v > m) m = v;
        }
        if (lane == 0) wmax[warp] = m;
        __syncthreads();
        if (warp == 0) {
            unsigned long long v = wmax[lane];
#pragma unroll
            for (int o = 16; o > 0; o >>= 1) {
                unsigned long long v2 = __shfl_down_sync(0xffffffffu, v, o);
                if (v2 > v) v = v2;
            }
            if (lane == 0) smax = v;
        }
        __syncthreads();
        unsigned long long gm = smax;

        if (gm == 0ull) {
            if (t == 0) *(float4*)(outp + it * 4) = make_float4(0.f, 0.f, 0.f, 0.f);
            __syncthreads();
            continue;
        }
#pragma unroll
        for (int e = 0; e < 6; ++e) {
            if (lk[e] == gm) {
                ssel = lb[e];
                *(float4*)(outp + it * 4) = lb[e];
                lk[e] = 0ull;
            }
        }
        __syncthreads();
        float4 s = ssel;
        float sa = fmaxf(s.z - s.x, 0.f) * fmaxf(s.w - s.y, 0.f);
#pragma unroll
        for (int e = 0; e < 6; ++e) {
            if (lk[e] != 0ull) {
                float yy1 = fmaxf(s.x, lb[e].x);
                float xx1 = fmaxf(s.y, lb[e].y);
                float yy2 = fminf(s.z, lb[e].z);
                float xx2 = fminf(s.w, lb[e].w);
                float inter = fmaxf(yy2 - yy1, 0.f) * fmaxf(xx2 - xx1, 0.f);
                float a2 = fmaxf(lb[e].z - lb[e].x, 0.f) * fmaxf(lb[e].w - lb[e].y, 0.f);
                float iou = inter / (sa + a2 - inter + 1e-8f);
                if (iou > 0.7f) lk[e] = 0ull;
            }
        }
        __syncthreads();
    }
}

// ---------------- launch ----------------
extern "C" void kernel_launch(void* const* d_in, const int* in_sizes, int n_in,
                              void* d_out, int out_size) {
    const float* fm = (const float*)d_in[1];
    const float* am = (const float*)d_in[2];
    const float* W1 = (const float*)d_in[4];
    const float* b1 = (const float*)d_in[5];
    const float* Wc = (const float*)d_in[6];
    const float* bc = (const float*)d_in[7];
    const float* Wr = (const float*)d_in[8];
    const float* br = (const float*)d_in[9];
    float* out = (float*)d_out;

    k_reset<<<12, 256>>>(Wc, Wr);
    k_prep<<<dim3(500, 16, 9), dim3(32, 8)>>>(fm);
    k_conv3<<<dim3(125, 4), 256>>>(W1, b1);
    k_head<<<1000, 256>>>(bc, br, out);
    k_decode<<<(NANCH + 255) / 256, 256>>>(am, out);
    for (int b = 7; b >= 0; --b) {
        k_hist<<<148, 256>>>(b);
        k_scan<<<1, 1>>>(b);
    }
    k_compact<<<(NANCH + 255) / 256, 256>>>();
    k_nms<<<1, 1024>>>(out);
}

// round 13
// speedup vs baseline: 1.0542x; 1.0203x over previous
#include <cuda_runtime.h>
#include <cstdint>

// ---------------- problem constants ----------------
#define FH_   100
#define FW_   160
#define NPOS  16000          // FH*FW
#define CIN   512
#define KTOT  4608           // 9*512
#define NANCH 144000         // NPOS*9
#define PRE_NMS_  6000
#define POST_NMS_ 300
#define IMG_H 1600.0f
#define IMG_W 2560.0f

#define OFF_SCORES 0
#define OFF_REG    144000
#define OFF_PROPS  720000

// ---------------- scratch (device globals; no allocation allowed) ----------------
__device__ float              g_AT[(size_t)KTOT * NPOS];  // 295MB zero-padded im2col^T
__device__ float              g_y[NPOS * 512];            // conv1 output
__device__ float              g_wT[45 * 512];             // head weights transposed [o][k]
__device__ float4             g_props[NANCH];
__device__ unsigned long long g_keys[NANCH];
__device__ unsigned long long g_cand_keys[PRE_NMS_];
__device__ float4             g_cand_boxes[PRE_NMS_];
__device__ unsigned int       g_hist[256];
__device__ unsigned long long g_prefix;
__device__ unsigned int       g_rank;
__device__ unsigned int       g_done;
__device__ unsigned int       g_count;

// ---------------- helpers ----------------
__device__ __forceinline__ uint32_t s2u(const void* p) {
    uint32_t a;
    asm("{ .reg .u64 t; cvta.to.shared.u64 t, %1; cvt.u32.u64 %0, t; }" : "=r"(a) : "l"(p));
    return a;
}
__device__ __forceinline__ void cp16(uint32_t dst, const void* src) {
    asm volatile("cp.async.cg.shared.global [%0], [%1], 16;" :: "r"(dst), "l"(src));
}

// ---------------- reset + head-weight transpose (merged) ----------------
__global__ void k_reset(const float* __restrict__ Wc, const float* __restrict__ Wr) {
    int t = blockIdx.x * 256 + threadIdx.x;
    if (t < 256) g_hist[t] = 0u;
    if (t == 0) { g_prefix = 0ull; g_rank = PRE_NMS_; g_done = 0u; g_count = 0u; }
    for (int i = t; i < 45 * 512; i += gridDim.x * 256) {
        int o = i >> 9, k = i & 511;
        g_wT[o * 512 + k] = (o < 9) ? Wc[k * 9 + o] : Wr[k * 36 + (o - 9)];
    }
}

// ---------------- prep: build zero-padded im2col transpose AT[k][m] ----------------
__global__ __launch_bounds__(256)
void k_prep(const float* __restrict__ fm) {
    __shared__ float ts[32][33];
    const int tx = threadIdx.x;      // 0..31
    const int ty = threadIdx.y;      // 0..7
    const int m0  = blockIdx.x * 32;
    const int ci0 = blockIdx.y * 32;
    const int tap = blockIdx.z;
    const int dh = tap / 3 - 1, dw = tap % 3 - 1;
    const int delta = dh * FW_ + dw;

    for (int r = ty; r < 32; r += 8) {
        int m = m0 + r;
        int h = m / FW_, w = m % FW_;
        bool ok = ((unsigned)(h + dh) < FH_) && ((unsigned)(w + dw) < FW_);
        ts[r][tx] = ok ? fm[(size_t)(m + delta) * 512 + ci0 + tx] : 0.f;
    }
    __syncthreads();
    for (int r = ty; r < 32; r += 8) {
        g_AT[(size_t)(tap * 512 + ci0 + r) * NPOS + m0 + tx] = ts[tx][r];
    }
}

// ---------------- 3x3 conv as GEMM: C[16000,512] = AT^T * W1 (UNCHANGED, bit-exact) ----
#define BK   16
#define NKT  (KTOT / BK)     // 288

__global__ __launch_bounds__(256, 2)
void k_conv3(const float* __restrict__ W1, const float* __restrict__ b1) {
    __shared__ float As[3][BK][128];
    __shared__ float Bs[3][BK][128];

    const int t  = threadIdx.x;
    const int m0 = blockIdx.x * 128;
    const int n0 = blockIdx.y * 128;
    const int tx = t & 15, ty = t >> 4;

    float acc[8][8];
#pragma unroll
    for (int i = 0; i < 8; ++i)
#pragma unroll
        for (int j = 0; j < 8; ++j) acc[i][j] = 0.f;

    auto loads = [&](int kt, int stg) {
        int K0 = kt * BK;
#pragma unroll
        for (int s = 0; s < 2; ++s) {
            int c  = t + s * 256;
            int k  = c >> 5;
            int mc = (c & 31) * 4;
            cp16(s2u(&As[stg][k][mc]), g_AT + (size_t)(K0 + k) * NPOS + m0 + mc);
            cp16(s2u(&Bs[stg][k][mc]), W1 + (size_t)(K0 + k) * 512 + n0 + mc);
        }
        asm volatile("cp.async.commit_group;" ::: "memory");
    };

    loads(0, 0);
    loads(1, 1);

    for (int kt = 0; kt < NKT; ++kt) {
        if (kt == NKT - 1) asm volatile("cp.async.wait_group 0;" ::: "memory");
        else               asm volatile("cp.async.wait_group 1;" ::: "memory");
        __syncthreads();
        if (kt + 2 < NKT) loads(kt + 2, (kt + 2) % 3);

        const int stg = kt % 3;
#pragma unroll
        for (int k = 0; k < BK; ++k) {
            float4 a0  = *(float4*)&As[stg][k][ty * 8];
            float4 a1  = *(float4*)&As[stg][k][ty * 8 + 4];
            float4 b0  = *(float4*)&Bs[stg][k][tx * 8];
            float4 b1v = *(float4*)&Bs[stg][k][tx * 8 + 4];
            float av[8] = {a0.x, a0.y, a0.z, a0.w, a1.x, a1.y, a1.z, a1.w};
            float bv[8] = {b0.x, b0.y, b0.z, b0.w, b1v.x, b1v.y, b1v.z, b1v.w};
#pragma unroll
            for (int i = 0; i < 8; ++i)
#pragma unroll
                for (int j = 0; j < 8; ++j) acc[i][j] += av[i] * bv[j];
        }
        __syncthreads();
    }

    float bs[8];
#pragma unroll
    for (int j = 0; j < 8; ++j) bs[j] = b1[n0 + tx * 8 + j];

#pragma unroll
    for (int i = 0; i < 8; ++i) {
        int pos = m0 + ty * 8 + i;
        float o[8];
#pragma unroll
        for (int j = 0; j < 8; ++j) o[j] = fmaxf(acc[i][j] + bs[j], 0.f);
        float* dst = g_y + (size_t)pos * 512 + n0 + tx * 8;
        *(float4*)(dst)     = make_float4(o[0], o[1], o[2], o[3]);
        *(float4*)(dst + 4) = make_float4(o[4], o[5], o[6], o[7]);
    }
}

// ---------------- 1x1 head convs + sigmoid: 3 dots per thread (ILP=3) ---------------
// Per-dot accumulation order is unchanged (k-ascending, x,y,z,w) -> bit-identical out.
#define SYROW 516
__global__ __launch_bounds__(256)
void k_head(const float* __restrict__ bc, const float* __restrict__ br,
            float* __restrict__ out) {
    __shared__ float sy[16 * SYROW];
    const int t  = threadIdx.x;
    const int p0 = blockIdx.x * 16;

    {
        const float4* src = (const float4*)(g_y + (size_t)p0 * 512);
        for (int i = t; i < 16 * 128; i += 256) {
            int pos = i >> 7, c = i & 127;
            ((float4*)(sy + pos * SYROW))[c] = src[i];
        }
    }
    __syncthreads();

    const int oBase = t >> 4;     // 0..15 -> o, o+16, o+32
    const int pos   = t & 15;
    const bool has2 = (oBase + 32) < 45;

    const float4* y4 = (const float4*)(sy + pos * SYROW);
    const float4* w0 = (const float4*)(g_wT + oBase * 512);
    const float4* w1 = (const float4*)(g_wT + (oBase + 16) * 512);
    const float4* w2 = (const float4*)(g_wT + (has2 ? (oBase + 32) : (oBase + 16)) * 512);

    float acc0 = 0.f, acc1 = 0.f, acc2 = 0.f;
#pragma unroll 4
    for (int k4 = 0; k4 < 128; ++k4) {
        float4 yv = y4[k4];
        float4 a  = w0[k4];
        float4 b  = w1[k4];
        float4 c  = w2[k4];
        acc0 += yv.x * a.x; acc1 += yv.x * b.x; acc2 += yv.x * c.x;
        acc0 += yv.y * a.y; acc1 += yv.y * b.y; acc2 += yv.y * c.y;
        acc0 += yv.z * a.z; acc1 += yv.z * b.z; acc2 += yv.z * c.z;
        acc0 += yv.w * a.w; acc1 += yv.w * b.w; acc2 += yv.w * c.w;
    }

    const int gp = p0 + pos;
    // o = oBase (0..15): scores for <9, else reg
    if (oBase < 9) {
        float v = acc0 + bc[oBase];
        out[OFF_SCORES + gp * 9 + oBase] = 1.f / (1.f + expf(-v));
    } else {
        out[OFF_REG + gp * 36 + (oBase - 9)] = acc0 + br[oBase - 9];
    }
    // o = oBase+16 (16..31): reg
    out[OFF_REG + gp * 36 + (oBase + 16 - 9)] = acc1 + br[oBase + 16 - 9];
    // o = oBase+32 (32..44): reg
    if (has2)
        out[OFF_REG + gp * 36 + (oBase + 32 - 9)] = acc2 + br[oBase + 32 - 9];
}

// ---------------- decode anchors + build sort keys ----------------
__global__ void k_decode(const float* __restrict__ am, const float* __restrict__ out) {
    int i = blockIdx.x * 256 + threadIdx.x;
    if (i >= NANCH) return;
    float  s = out[OFF_SCORES + i];
    float4 d = *(const float4*)(out + OFF_REG + (size_t)i * 4);
    float4 A = *(const float4*)(am + (size_t)i * 4);

    float ah = A.z - A.x, aw = A.w - A.y;
    float acy = A.x + 0.5f * ah, acx = A.y + 0.5f * aw;
    float cy = acy + d.x * ah, cx = acx + d.y * aw;
    float hh = ah * expf(d.z), ww = aw * expf(d.w);
    g_props[i] = make_float4(cy - 0.5f * hh, cx - 0.5f * ww, cy + 0.5f * hh, cx + 0.5f * ww);

    unsigned int ob = __float_as_uint(s) | 0x80000000u;
    g_keys[i] = ((unsigned long long)ob << 32) | (unsigned long long)(0xFFFFFFFFu - (unsigned)i);
}

// ---------------- exact top-6000: MSD radix select with early exit ----------------
__global__ void k_hist(int b) {
    __shared__ unsigned int sh[256];
    __shared__ unsigned int s_done;
    int t = threadIdx.x;
    if (t == 0) s_done = g_done;
    if (t < 256) sh[t] = 0u;
    __syncthreads();
    if (s_done) return;
    unsigned long long pref = g_prefix;
    int shift = (b + 1) * 8;
    for (int i = blockIdx.x * blockDim.x + t; i < NANCH; i += gridDim.x * blockDim.x) {
        unsigned long long k = g_keys[i];
        if (b == 7 || (k >> shift) == (pref >> shift))
            atomicAdd(&sh[(unsigned int)(k >> (b * 8)) & 255u], 1u);
    }
    __syncthreads();
    if (t < 256 && sh[t]) atomicAdd(&g_hist[t], sh[t]);
}

__global__ void k_scan(int b) {
    if (threadIdx.x != 0) return;
    if (g_done) return;
    unsigned int r = g_rank, cum = 0, c = 0;
    int d = 255;
    for (; d >= 0; --d) {
        c = g_hist[d];
        if (cum + c >= r) break;
        cum += c;
    }
    if (d < 0) { d = 0; c = 0; }
    g_prefix |= ((unsigned long long)(unsigned int)d) << (b * 8);
    unsigned int need = r - cum;
    g_rank = need;
    if (c == need) g_done = 1u;
    for (int j = 0; j < 256; ++j) g_hist[j] = 0u;
}

// ---------------- compact top-6000, clip + min-size filter ----------------
__global__ void k_compact() {
    int i = blockIdx.x * 256 + threadIdx.x;
    if (i >= NANCH) return;
    unsigned long long k = g_keys[i];
    if (k >= g_prefix) {
        unsigned int slot = atomicAdd(&g_count, 1u);
        float4 pr = g_props[i];
        float y1 = fmaxf(pr.x, 0.f), x1 = fmaxf(pr.y, 0.f);
        float y2 = fminf(pr.z, IMG_H), x2 = fminf(pr.w, IMG_W);
        float hh = y2 - y1, ww = x2 - x1;
        if (!(hh >= 16.f && ww >= 16.f)) k = 0ull;
        g_cand_keys[slot]  = k;
        g_cand_boxes[slot] = make_float4(y1, x1, y2, x2);
    }
}

// ---------------- greedy NMS: single block, register-resident (UNCHANGED) -----------
__global__ __launch_bounds__(1024)
void k_nms(float* __restrict__ out) {
    __shared__ unsigned long long wmax[32];
    __shared__ unsigned long long smax;
    __shared__ float4 ssel;

    const int t = threadIdx.x, lane = t & 31, warp = t >> 5;
    unsigned long long lk[6];
    float4 lb[6];
#pragma unroll
    for (int e = 0; e < 6; ++e) {
        int idx = e * 1024 + t;
        if (idx < PRE_NMS_) { lk[e] = g_cand_keys[idx]; lb[e] = g_cand_boxes[idx]; }
        else                { lk[e] = 0ull; lb[e] = make_float4(0.f, 0.f, 0.f, 0.f); }
    }
    float* outp = out + OFF_PROPS;

    for (int it = 0; it < POST_NMS_; ++it) {
        unsigned long long m = lk[0];
#pragma unroll
        for (int e = 1; e < 6; ++e) m = (lk[e] > m) ? lk[e] : m;
#pragma unroll
        for (int o = 16; o > 0; o >>= 1) {
            unsigned long long v = __shfl_down_sync(0xffffffffu, m, o);
            if (v > m) m = v;
        }
        if (lane == 0) wmax[warp] = m;
        __syncthreads();
        if (warp == 0) {
            unsigned long long v = wmax[lane];
#pragma unroll
            for (int o = 16; o > 0; o >>= 1) {
                unsigned long long v2 = __shfl_down_sync(0xffffffffu, v, o);
                if (v2 > v) v = v2;
            }
            if (lane == 0) smax = v;
        }
        __syncthreads();
        unsigned long long gm = smax;

        if (gm == 0ull) {
            if (t == 0) *(float4*)(outp + it * 4) = make_float4(0.f, 0.f, 0.f, 0.f);
            __syncthreads();
            continue;
        }
#pragma unroll
        for (int e = 0; e < 6; ++e) {
            if (lk[e] == gm) {
                ssel = lb[e];
                *(float4*)(outp + it * 4) = lb[e];
                lk[e] = 0ull;
            }
        }
        __syncthreads();
        float4 s = ssel;
        float sa = fmaxf(s.z - s.x, 0.f) * fmaxf(s.w - s.y, 0.f);
#pragma unroll
        for (int e = 0; e < 6; ++e) {
            if (lk[e] != 0ull) {
                float yy1 = fmaxf(s.x, lb[e].x);
                float xx1 = fmaxf(s.y, lb[e].y);
                float yy2 = fminf(s.z, lb[e].z);
                float xx2 = fminf(s.w, lb[e].w);
                float inter = fmaxf(yy2 - yy1, 0.f) * fmaxf(xx2 - xx1, 0.f);
                float a2 = fmaxf(lb[e].z - lb[e].x, 0.f) * fmaxf(lb[e].w - lb[e].y, 0.f);
                float iou = inter / (sa + a2 - inter + 1e-8f);
                if (iou > 0.7f) lk[e] = 0ull;
            }
        }
        __syncthreads();
    }
}

// ---------------- launch ----------------
extern "C" void kernel_launch(void* const* d_in, const int* in_sizes, int n_in,
                              void* d_out, int out_size) {
    const float* fm = (const float*)d_in[1];
    const float* am = (const float*)d_in[2];
    const float* W1 = (const float*)d_in[4];
    const float* b1 = (const float*)d_in[5];
    const float* Wc = (const float*)d_in[6];
    const float* bc = (const float*)d_in[7];
    const float* Wr = (const float*)d_in[8];
    const float* br = (const float*)d_in[9];
    float* out = (float*)d_out;

    k_reset<<<12, 256>>>(Wc, Wr);
    k_prep<<<dim3(500, 16, 9), dim3(32, 8)>>>(fm);
    k_conv3<<<dim3(125, 4), 256>>>(W1, b1);
    k_head<<<1000, 256>>>(bc, br, out);
    k_decode<<<(NANCH + 255) / 256, 256>>>(am, out);
    for (int b = 7; b >= 0; --b) {
        k_hist<<<148, 256>>>(b);
        k_scan<<<1, 1>>>(b);
    }
    k_compact<<<(NANCH + 255) / 256, 256>>>();
    k_nms<<<1, 1024>>>(out);
}

// round 14
// speedup vs baseline: 1.0597x; 1.0053x over previous
#include <cuda_runtime.h>
#include <cstdint>

// ---------------- problem constants ----------------
#define FH_   100
#define FW_   160
#define NPOS  16000          // FH*FW
#define CIN   512
#define KTOT  4608           // 9*512
#define NANCH 144000         // NPOS*9
#define PRE_NMS_  6000
#define POST_NMS_ 300
#define IMG_H 1600.0f
#define IMG_W 2560.0f

#define OFF_SCORES 0
#define OFF_REG    144000
#define OFF_PROPS  720000

#define CONV_CTAS   296      // 148 SMs x 2 resident CTAs
#define CONV_TILES  500      // 125 m-tiles x 4 n-tiles

// ---------------- scratch (device globals; no allocation allowed) ----------------
__device__ float              g_AT[(size_t)KTOT * NPOS];  // 295MB zero-padded im2col^T
__device__ float              g_y[NPOS * 512];            // conv1 output
__device__ float              g_wT[45 * 512];             // head weights transposed [o][k]
__device__ float4             g_props[NANCH];
__device__ unsigned long long g_keys[NANCH];
__device__ unsigned long long g_cand_keys[PRE_NMS_];
__device__ float4             g_cand_boxes[PRE_NMS_];
__device__ unsigned int       g_hist[256];
__device__ unsigned long long g_prefix;
__device__ unsigned int       g_rank;
__device__ unsigned int       g_done;
__device__ unsigned int       g_count;
__device__ unsigned int       g_tile;

// ---------------- helpers ----------------
__device__ __forceinline__ uint32_t s2u(const void* p) {
    uint32_t a;
    asm("{ .reg .u64 t; cvta.to.shared.u64 t, %1; cvt.u32.u64 %0, t; }" : "=r"(a) : "l"(p));
    return a;
}
__device__ __forceinline__ void cp16(uint32_t dst, const void* src) {
    asm volatile("cp.async.cg.shared.global [%0], [%1], 16;" :: "r"(dst), "l"(src));
}

// ---------------- reset + head-weight transpose (merged) ----------------
__global__ void k_reset(const float* __restrict__ Wc, const float* __restrict__ Wr) {
    int t = blockIdx.x * 256 + threadIdx.x;
    if (t < 256) g_hist[t] = 0u;
    if (t == 0) { g_prefix = 0ull; g_rank = PRE_NMS_; g_done = 0u; g_count = 0u; g_tile = 0u; }
    for (int i = t; i < 45 * 512; i += gridDim.x * 256) {
        int o = i >> 9, k = i & 511;
        g_wT[o * 512 + k] = (o < 9) ? Wc[k * 9 + o] : Wr[k * 36 + (o - 9)];
    }
}

// ---------------- prep: build zero-padded im2col transpose AT[k][m] ----------------
__global__ __launch_bounds__(256)
void k_prep(const float* __restrict__ fm) {
    __shared__ float ts[32][33];
    const int tx = threadIdx.x;      // 0..31
    const int ty = threadIdx.y;      // 0..7
    const int m0  = blockIdx.x * 32;
    const int ci0 = blockIdx.y * 32;
    const int tap = blockIdx.z;
    const int dh = tap / 3 - 1, dw = tap % 3 - 1;
    const int delta = dh * FW_ + dw;

    for (int r = ty; r < 32; r += 8) {
        int m = m0 + r;
        int h = m / FW_, w = m % FW_;
        bool ok = ((unsigned)(h + dh) < FH_) && ((unsigned)(w + dw) < FW_);
        ts[r][tx] = ok ? fm[(size_t)(m + delta) * 512 + ci0 + tx] : 0.f;
    }
    __syncthreads();
    for (int r = ty; r < 32; r += 8) {
        g_AT[(size_t)(tap * 512 + ci0 + r) * NPOS + m0 + tx] = ts[tx][r];
    }
}

// ---------------- 3x3 conv as GEMM, persistent CTAs + dynamic tile stealing --------
// Per-tile arithmetic/memory schedule is BYTE-IDENTICAL to the R13 kernel; only the
// CTA<->tile assignment is dynamic (bit-exact output, balanced waves).
#define BK   16
#define NKT  (KTOT / BK)     // 288

__global__ __launch_bounds__(256, 2)
void k_conv3(const float* __restrict__ W1, const float* __restrict__ b1) {
    __shared__ float As[3][BK][128];
    __shared__ float Bs[3][BK][128];
    __shared__ unsigned int s_tile;

    const int t  = threadIdx.x;
    const int tx = t & 15, ty = t >> 4;

    while (true) {
        if (t == 0) s_tile = atomicAdd(&g_tile, 1u);
        __syncthreads();
        const unsigned int tile = s_tile;
        if (tile >= CONV_TILES) break;
        const int m0 = (int)(tile % 125) * 128;
        const int n0 = (int)(tile / 125) * 128;

        float acc[8][8];
#pragma unroll
        for (int i = 0; i < 8; ++i)
#pragma unroll
            for (int j = 0; j < 8; ++j) acc[i][j] = 0.f;

        auto loads = [&](int kt, int stg) {
            int K0 = kt * BK;
#pragma unroll
            for (int s = 0; s < 2; ++s) {
                int c  = t + s * 256;
                int k  = c >> 5;
                int mc = (c & 31) * 4;
                cp16(s2u(&As[stg][k][mc]), g_AT + (size_t)(K0 + k) * NPOS + m0 + mc);
                cp16(s2u(&Bs[stg][k][mc]), W1 + (size_t)(K0 + k) * 512 + n0 + mc);
            }
            asm volatile("cp.async.commit_group;" ::: "memory");
        };

        loads(0, 0);
        loads(1, 1);

        for (int kt = 0; kt < NKT; ++kt) {
            if (kt == NKT - 1) asm volatile("cp.async.wait_group 0;" ::: "memory");
            else               asm volatile("cp.async.wait_group 1;" ::: "memory");
            __syncthreads();
            if (kt + 2 < NKT) loads(kt + 2, (kt + 2) % 3);

            const int stg = kt % 3;
#pragma unroll
            for (int k = 0; k < BK; ++k) {
                float4 a0  = *(float4*)&As[stg][k][ty * 8];
                float4 a1  = *(float4*)&As[stg][k][ty * 8 + 4];
                float4 b0  = *(float4*)&Bs[stg][k][tx * 8];
                float4 b1v = *(float4*)&Bs[stg][k][tx * 8 + 4];
                float av[8] = {a0.x, a0.y, a0.z, a0.w, a1.x, a1.y, a1.z, a1.w};
                float bv[8] = {b0.x, b0.y, b0.z, b0.w, b1v.x, b1v.y, b1v.z, b1v.w};
#pragma unroll
                for (int i = 0; i < 8; ++i)
#pragma unroll
                    for (int j = 0; j < 8; ++j) acc[i][j] += av[i] * bv[j];
            }
            __syncthreads();
        }

        float bs[8];
#pragma unroll
        for (int j = 0; j < 8; ++j) bs[j] = b1[n0 + tx * 8 + j];

#pragma unroll
        for (int i = 0; i < 8; ++i) {
            int pos = m0 + ty * 8 + i;
            float o[8];
#pragma unroll
            for (int j = 0; j < 8; ++j) o[j] = fmaxf(acc[i][j] + bs[j], 0.f);
            float* dst = g_y + (size_t)pos * 512 + n0 + tx * 8;
            *(float4*)(dst)     = make_float4(o[0], o[1], o[2], o[3]);
            *(float4*)(dst + 4) = make_float4(o[4], o[5], o[6], o[7]);
        }
    }
}

// ---------------- 1x1 head convs + sigmoid: 3 channels x 2 positions (ILP=6) --------
// Per-dot accumulation order unchanged (k-ascending, x,y,z,w) -> bit-identical out.
#define SYROW 516
__global__ __launch_bounds__(128)
void k_head(const float* __restrict__ bc, const float* __restrict__ br,
            float* __restrict__ out) {
    __shared__ float sy[16 * SYROW];
    const int t  = threadIdx.x;            // 0..127
    const int p0 = blockIdx.x * 16;

    {
        const float4* src = (const float4*)(g_y + (size_t)p0 * 512);
        for (int i = t; i < 16 * 128; i += 128) {
            int pos = i >> 7, c = i & 127;
            ((float4*)(sy + pos * SYROW))[c] = src[i];
        }
    }
    __syncthreads();

    const int oBase = t >> 3;              // 0..15 -> channels o, o+16, o+32
    const int pp    = t & 7;               // position pair: pp, pp+8
    const bool has2 = (oBase + 32) < 45;

    const float4* y0 = (const float4*)(sy + pp * SYROW);
    const float4* y1 = (const float4*)(sy + (pp + 8) * SYROW);
    const float4* w0 = (const float4*)(g_wT + oBase * 512);
    const float4* w1 = (const float4*)(g_wT + (oBase + 16) * 512);
    const float4* w2 = (const float4*)(g_wT + (has2 ? (oBase + 32) : (oBase + 16)) * 512);

    float a00 = 0.f, a01 = 0.f, a02 = 0.f;   // pos pp:   ch o, o+16, o+32
    float a10 = 0.f, a11 = 0.f, a12 = 0.f;   // pos pp+8
#pragma unroll 4
    for (int k4 = 0; k4 < 128; ++k4) {
        float4 v0 = y0[k4];
        float4 v1 = y1[k4];
        float4 a  = w0[k4];
        float4 b  = w1[k4];
        float4 c  = w2[k4];
        a00 += v0.x * a.x; a01 += v0.x * b.x; a02 += v0.x * c.x;
        a10 += v1.x * a.x; a11 += v1.x * b.x; a12 += v1.x * c.x;
        a00 += v0.y * a.y; a01 += v0.y * b.y; a02 += v0.y * c.y;
        a10 += v1.y * a.y; a11 += v1.y * b.y; a12 += v1.y * c.y;
        a00 += v0.z * a.z; a01 += v0.z * b.z; a02 += v0.z * c.z;
        a10 += v1.z * a.z; a11 += v1.z * b.z; a12 += v1.z * c.z;
        a00 += v0.w * a.w; a01 += v0.w * b.w; a02 += v0.w * c.w;
        a10 += v1.w * a.w; a11 += v1.w * b.w; a12 += v1.w * c.w;
    }

    const int gp0 = p0 + pp;
    const int gp1 = p0 + pp + 8;
    if (oBase < 9) {
        float v0 = a00 + bc[oBase];
        float v1 = a10 + bc[oBase];
        out[OFF_SCORES + gp0 * 9 + oBase] = 1.f / (1.f + expf(-v0));
        out[OFF_SCORES + gp1 * 9 + oBase] = 1.f / (1.f + expf(-v1));
    } else {
        out[OFF_REG + gp0 * 36 + (oBase - 9)] = a00 + br[oBase - 9];
        out[OFF_REG + gp1 * 36 + (oBase - 9)] = a10 + br[oBase - 9];
    }
    out[OFF_REG + gp0 * 36 + (oBase + 16 - 9)] = a01 + br[oBase + 16 - 9];
    out[OFF_REG + gp1 * 36 + (oBase + 16 - 9)] = a11 + br[oBase + 16 - 9];
    if (has2) {
        out[OFF_REG + gp0 * 36 + (oBase + 32 - 9)] = a02 + br[oBase + 32 - 9];
        out[OFF_REG + gp1 * 36 + (oBase + 32 - 9)] = a12 + br[oBase + 32 - 9];
    }
}

// ---------------- decode anchors + build sort keys ----------------
__global__ void k_decode(const float* __restrict__ am, const float* __restrict__ out) {
    int i = blockIdx.x * 256 + threadIdx.x;
    if (i >= NANCH) return;
    float  s = out[OFF_SCORES + i];
    float4 d = *(const float4*)(out + OFF_REG + (size_t)i * 4);
    float4 A = *(const float4*)(am + (size_t)i * 4);

    float ah = A.z - A.x, aw = A.w - A.y;
    float acy = A.x + 0.5f * ah, acx = A.y + 0.5f * aw;
    float cy = acy + d.x * ah, cx = acx + d.y * aw;
    float hh = ah * expf(d.z), ww = aw * expf(d.w);
    g_props[i] = make_float4(cy - 0.5f * hh, cx - 0.5f * ww, cy + 0.5f * hh, cx + 0.5f * ww);

    unsigned int ob = __float_as_uint(s) | 0x80000000u;
    g_keys[i] = ((unsigned long long)ob << 32) | (unsigned long long)(0xFFFFFFFFu - (unsigned)i);
}

// ---------------- exact top-6000: MSD radix select with early exit ----------------
__global__ void k_hist(int b) {
    __shared__ unsigned int sh[256];
    __shared__ unsigned int s_done;
    int t = threadIdx.x;
    if (t == 0) s_done = g_done;
    if (t < 256) sh[t] = 0u;
    __syncthreads();
    if (s_done) return;
    unsigned long long pref = g_prefix;
    int shift = (b + 1) * 8;
    for (int i = blockIdx.x * blockDim.x + t; i < NANCH; i += gridDim.x * blockDim.x) {
        unsigned long long k = g_keys[i];
        if (b == 7 || (k >> shift) == (pref >> shift))
            atomicAdd(&sh[(unsigned int)(k >> (b * 8)) & 255u], 1u);
    }
    __syncthreads();
    if (t < 256 && sh[t]) atomicAdd(&g_hist[t], sh[t]);
}

__global__ void k_scan(int b) {
    if (threadIdx.x != 0) return;
    if (g_done) return;
    unsigned int r = g_rank, cum = 0, c = 0;
    int d = 255;
    for (; d >= 0; --d) {
        c = g_hist[d];
        if (cum + c >= r) break;
        cum += c;
    }
    if (d < 0) { d = 0; c = 0; }
    g_prefix |= ((unsigned long long)(unsigned int)d) << (b * 8);
    unsigned int need = r - cum;
    g_rank = need;
    if (c == need) g_done = 1u;
    for (int j = 0; j < 256; ++j) g_hist[j] = 0u;
}

// ---------------- compact top-6000, clip + min-size filter ----------------
__global__ void k_compact() {
    int i = blockIdx.x * 256 + threadIdx.x;
    if (i >= NANCH) return;
    unsigned long long k = g_keys[i];
    if (k >= g_prefix) {
        unsigned int slot = atomicAdd(&g_count, 1u);
        float4 pr = g_props[i];
        float y1 = fmaxf(pr.x, 0.f), x1 = fmaxf(pr.y, 0.f);
        float y2 = fminf(pr.z, IMG_H), x2 = fminf(pr.w, IMG_W);
        float hh = y2 - y1, ww = x2 - x1;
        if (!(hh >= 16.f && ww >= 16.f)) k = 0ull;
        g_cand_keys[slot]  = k;
        g_cand_boxes[slot] = make_float4(y1, x1, y2, x2);
    }
}

// ---------------- greedy NMS: single block, register-resident (UNCHANGED) -----------
__global__ __launch_bounds__(1024)
void k_nms(float* __restrict__ out) {
    __shared__ unsigned long long wmax[32];
    __shared__ unsigned long long smax;
    __shared__ float4 ssel;

    const int t = threadIdx.x, lane = t & 31, warp = t >> 5;
    unsigned long long lk[6];
    float4 lb[6];
#pragma unroll
    for (int e = 0; e < 6; ++e) {
        int idx = e * 1024 + t;
        if (idx < PRE_NMS_) { lk[e] = g_cand_keys[idx]; lb[e] = g_cand_boxes[idx]; }
        else                { lk[e] = 0ull; lb[e] = make_float4(0.f, 0.f, 0.f, 0.f); }
    }
    float* outp = out + OFF_PROPS;

    for (int it = 0; it < POST_NMS_; ++it) {
        unsigned long long m = lk[0];
#pragma unroll
        for (int e = 1; e < 6; ++e) m = (lk[e] > m) ? lk[e] : m;
#pragma unroll
        for (int o = 16; o > 0; o >>= 1) {
            unsigned long long v = __shfl_down_sync(0xffffffffu, m, o);
            if (v > m) m = v;
        }
        if (lane == 0) wmax[warp] = m;
        __syncthreads();
        if (warp == 0) {
            unsigned long long v = wmax[lane];
#pragma unroll
            for (int o = 16; o > 0; o >>= 1) {
                unsigned long long v2 = __shfl_down_sync(0xffffffffu, v, o);
                if (v2 > v) v = v2;
            }
            if (lane == 0) smax = v;
        }
        __syncthreads();
        unsigned long long gm = smax;

        if (gm == 0ull) {
            if (t == 0) *(float4*)(outp + it * 4) = make_float4(0.f, 0.f, 0.f, 0.f);
            __syncthreads();
            continue;
        }
#pragma unroll
        for (int e = 0; e < 6; ++e) {
            if (lk[e] == gm) {
                ssel = lb[e];
                *(float4*)(outp + it * 4) = lb[e];
                lk[e] = 0ull;
            }
        }
        __syncthreads();
        float4 s = ssel;
        float sa = fmaxf(s.z - s.x, 0.f) * fmaxf(s.w - s.y, 0.f);
#pragma unroll
        for (int e = 0; e < 6; ++e) {
            if (lk[e] != 0ull) {
                float yy1 = fmaxf(s.x, lb[e].x);
                float xx1 = fmaxf(s.y, lb[e].y);
                float yy2 = fminf(s.z, lb[e].z);
                float xx2 = fminf(s.w, lb[e].w);
                float inter = fmaxf(yy2 - yy1, 0.f) * fmaxf(xx2 - xx1, 0.f);
                float a2 = fmaxf(lb[e].z - lb[e].x, 0.f) * fmaxf(lb[e].w - lb[e].y, 0.f);
                float iou = inter / (sa + a2 - inter + 1e-8f);
                if (iou > 0.7f) lk[e] = 0ull;
            }
        }
        __syncthreads();
    }
}

// ---------------- launch ----------------
extern "C" void kernel_launch(void* const* d_in, const int* in_sizes, int n_in,
                              void* d_out, int out_size) {
    const float* fm = (const float*)d_in[1];
    const float* am = (const float*)d_in[2];
    const float* W1 = (const float*)d_in[4];
    const float* b1 = (const float*)d_in[5];
    const float* Wc = (const float*)d_in[6];
    const float* bc = (const float*)d_in[7];
    const float* Wr = (const float*)d_in[8];
    const float* br = (const float*)d_in[9];
    float* out = (float*)d_out;

    k_reset<<<12, 256>>>(Wc, Wr);
    k_prep<<<dim3(500, 16, 9), dim3(32, 8)>>>(fm);
    k_conv3<<<CONV_CTAS, 256>>>(W1, b1);
    k_head<<<1000, 128>>>(bc, br, out);
    k_decode<<<(NANCH + 255) / 256, 256>>>(am, out);
    for (int b = 7; b >= 0; --b) {
        k_hist<<<148, 256>>>(b);
        k_scan<<<1, 1>>>(b);
    }
    k_compact<<<(NANCH + 255) / 256, 256>>>();
    k_nms<<<1, 1024>>>(out);
}